// round 15
// baseline (speedup 1.0000x reference)
#include <cuda_runtime.h>
#include <cuda_fp16.h>
#include <mma.h>
#include <cstdint>

using namespace nvcuda;

#define N_NODES 100000
#define N_EDGES 1600000
#define IN_DIM  165
#define HIDDEN  128
#define OUT_DIM 2

#define KSTEP  32
#define NITER  6              // 192 covered, zero-filled

#define SCAN_BLOCK 512
#define NB_SCAN ((N_NODES + SCAN_BLOCK - 1) / SCAN_BLOCK)

// gemm dynamic smem layout
#define SM_A32   0                      // 128x32 fp32 = 16384 B (epilogue stage overlays)
#define SM_AH    16384                  // 2 x 128x40 half = 20480 B
#define SM_BS    (16384 + 20480)        // 2 x 32x136 half = 17408 B
#define SM_GEMM  (16384 + 20480 + 17408)  // 54272 B

// ---------------------------------------------------------------------------
// Static scratch
// ---------------------------------------------------------------------------
__device__ __align__(16)  __half g_w1h[192 * HIDDEN];
__device__ __align__(256) __half g_h1h[(size_t)N_NODES * HIDDEN];   // UNSCALED fp16 h1
__device__ float g_h2s[(size_t)N_NODES * OUT_DIM];                  // dinv-scaled h2
__device__ float g_dinv[N_NODES];
__device__ int   g_cnt[N_NODES];
__device__ int   g_rowstart[N_NODES + 1];
__device__ int   g_cursor[N_NODES];
__device__ int   g_bsum[NB_SCAN];
__device__ int   g_bsum_ex[NB_SCAN];
__device__ int   g_csr_src[N_EDGES];

__device__ __forceinline__ void cp_async4(void* smem_dst, const void* gmem_src,
                                          int src_bytes) {
    uint32_t s = (uint32_t)__cvta_generic_to_shared(smem_dst);
    asm volatile("cp.async.ca.shared.global [%0], [%1], 4, %2;"
                 :: "r"(s), "l"(gmem_src), "r"(src_bytes));
}

__device__ __forceinline__ void cp_async16(void* smem_dst, const void* gmem_src,
                                           int src_bytes) {
    uint32_t s = (uint32_t)__cvta_generic_to_shared(smem_dst);
    asm volatile("cp.async.cg.shared.global [%0], [%1], 16, %2;"
                 :: "r"(s), "l"(gmem_src), "r"(src_bytes));
}

// ---------------------------------------------------------------------------
// W1 fp16 conversion (tiny)
// ---------------------------------------------------------------------------
__global__ void convert_w_kernel(const float* __restrict__ W) {
    int i = blockIdx.x * blockDim.x + threadIdx.x;
    if (i >= 192 * (HIDDEN / 2)) return;
    int r  = i / (HIDDEN / 2);
    int c2 = i % (HIDDEN / 2);
    int c  = c2 * 2;
    float a = (r < IN_DIM) ? W[(size_t)r * HIDDEN + c]     : 0.f;
    float b = (r < IN_DIM) ? W[(size_t)r * HIDDEN + c + 1] : 0.f;
    ((__half2*)g_w1h)[i] = __floats2half2_rn(a, b);
}

// ---------------------------------------------------------------------------
// degree / CSR build
// ---------------------------------------------------------------------------
__global__ void zero_cnt_kernel() {
    int i = blockIdx.x * blockDim.x + threadIdx.x;
    if (i < N_NODES) g_cnt[i] = 0;
}

__global__ void hist_kernel(const int* __restrict__ dst) {
    int i = blockIdx.x * blockDim.x + threadIdx.x;
    if (i >= N_EDGES / 4) return;
    int4 d = ((const int4*)dst)[i];
    atomicAdd(&g_cnt[d.x], 1);
    atomicAdd(&g_cnt[d.y], 1);
    atomicAdd(&g_cnt[d.z], 1);
    atomicAdd(&g_cnt[d.w], 1);
}

__global__ void dinv_kernel() {
    int i = blockIdx.x * blockDim.x + threadIdx.x;
    if (i < N_NODES) g_dinv[i] = rsqrtf((float)(g_cnt[i] + 1));
}

__global__ void scan1_kernel() {
    __shared__ int s0[SCAN_BLOCK], s1[SCAN_BLOCK];
    int t = threadIdx.x;
    int i = blockIdx.x * SCAN_BLOCK + t;
    int v = (i < N_NODES) ? g_cnt[i] : 0;
    int* a = s0; int* b = s1;
    a[t] = v;
    __syncthreads();
#pragma unroll
    for (int off = 1; off < SCAN_BLOCK; off <<= 1) {
        b[t] = (t >= off) ? a[t] + a[t - off] : a[t];
        __syncthreads();
        int* tmp = a; a = b; b = tmp;
    }
    if (i < N_NODES) g_rowstart[i] = a[t] - v;
    if (t == SCAN_BLOCK - 1) g_bsum[blockIdx.x] = a[t];
}

__global__ void scan2_kernel() {
    __shared__ int s0[SCAN_BLOCK], s1[SCAN_BLOCK];
    int t = threadIdx.x;
    int v = (t < NB_SCAN) ? g_bsum[t] : 0;
    int* a = s0; int* b = s1;
    a[t] = v;
    __syncthreads();
#pragma unroll
    for (int off = 1; off < SCAN_BLOCK; off <<= 1) {
        b[t] = (t >= off) ? a[t] + a[t - off] : a[t];
        __syncthreads();
        int* tmp = a; a = b; b = tmp;
    }
    if (t < NB_SCAN) g_bsum_ex[t] = a[t] - v;
}

__global__ void scan3_kernel() {
    int i = blockIdx.x * blockDim.x + threadIdx.x;
    if (i < N_NODES) {
        int r = g_rowstart[i] + g_bsum_ex[i / SCAN_BLOCK];
        g_rowstart[i] = r;
        g_cursor[i]   = r;
    } else if (i == N_NODES) {
        g_rowstart[N_NODES] = N_EDGES;
    }
}

__global__ void fill_edges_kernel(const int* __restrict__ src,
                                  const int* __restrict__ dst) {
    int e = blockIdx.x * blockDim.x + threadIdx.x;
    if (e < N_EDGES) {
        int d   = dst[e];
        int pos = atomicAdd(&g_cursor[d], 1);
        g_csr_src[pos] = src[e];
    }
}

// ---------------------------------------------------------------------------
// GEMM1 with fused X fp32->fp16 conversion; NO dinv dependency:
// h1h[r,:] = fp16(x[r,:] @ W1)   (unscaled)
// ---------------------------------------------------------------------------
__global__ void gemm1_fp16_kernel(const float* __restrict__ X) {
    extern __shared__ __align__(16) unsigned char sraw[];
    float* A32 = reinterpret_cast<float*>(sraw + SM_A32);
    __half (*Ah)[128][40] = reinterpret_cast<__half(*)[128][40]>(sraw + SM_AH);
    __half (*Bs)[32][136] = reinterpret_cast<__half(*)[32][136]>(sraw + SM_BS);
    float  (*stage)[16][20] = reinterpret_cast<float(*)[16][20]>(sraw);

    const int tid    = threadIdx.x;
    const int wid    = tid >> 5;
    const int lane   = tid & 31;
    const int warp_m = wid & 3;
    const int warp_n = wid >> 2;
    const int row0   = blockIdx.x * 128;

    auto load_a32 = [&](int k0) {
#pragma unroll
        for (int u = 0; u < 16; u++) {
            int idx = tid + u * 256;
            int r = idx >> 5, c = idx & 31;
            int gr = row0 + r, gc = k0 + c;
            int nb = (gr < N_NODES && gc < IN_DIM) ? 4 : 0;
            cp_async4(&A32[r * 32 + c], X + (size_t)gr * IN_DIM + gc, nb);
        }
    };
    auto load_bs = [&](int buf, int k0) {
#pragma unroll
        for (int t = 0; t < 2; t++) {
            int idx = tid + t * 256;
            int r = idx >> 4, ch = idx & 15;
            cp_async16(&Bs[buf][r][ch * 8],
                       g_w1h + (size_t)(k0 + r) * HIDDEN + ch * 8, 16);
        }
    };
    auto convert_a = [&](int buf) {
#pragma unroll
        for (int u = 0; u < 8; u++) {
            int idx = tid + u * 256;
            int r = idx >> 4, c2 = idx & 15;
            float2 f = ((const float2*)A32)[r * 16 + c2];
            *(__half2*)&Ah[buf][r][c2 * 2] = __floats2half2_rn(f.x, f.y);
        }
    };

    wmma::fragment<wmma::accumulator, 16, 16, 16, float> acc[2][4];
#pragma unroll
    for (int i = 0; i < 2; i++)
#pragma unroll
        for (int j = 0; j < 4; j++) wmma::fill_fragment(acc[i][j], 0.f);

    load_a32(0);
    load_bs(0, 0);
    asm volatile("cp.async.commit_group;");
    asm volatile("cp.async.wait_group 0;");
    __syncthreads();
    convert_a(0);
    __syncthreads();
    load_a32(KSTEP);
    load_bs(1, KSTEP);
    asm volatile("cp.async.commit_group;");

    for (int it = 0; it < NITER; it++) {
        int buf = it & 1;
        wmma::fragment<wmma::matrix_a, 16, 16, 16, __half, wmma::row_major> af[2];
        wmma::fragment<wmma::matrix_b, 16, 16, 16, __half, wmma::row_major> bf[4];
#pragma unroll
        for (int kk = 0; kk < KSTEP; kk += 16) {
#pragma unroll
            for (int i = 0; i < 2; i++)
                wmma::load_matrix_sync(af[i], &Ah[buf][warp_m * 32 + i * 16][kk], 40);
#pragma unroll
            for (int j = 0; j < 4; j++)
                wmma::load_matrix_sync(bf[j], &Bs[buf][kk][warp_n * 64 + j * 16], 136);
#pragma unroll
            for (int i = 0; i < 2; i++)
#pragma unroll
                for (int j = 0; j < 4; j++)
                    wmma::mma_sync(acc[i][j], af[i], bf[j], acc[i][j]);
        }
        if (it + 1 < NITER) {
            asm volatile("cp.async.wait_group 0;");
            __syncthreads();
            convert_a((it + 1) & 1);
            __syncthreads();
            if (it + 2 < NITER) {
                load_a32((it + 2) * KSTEP);
                load_bs(it & 1, (it + 2) * KSTEP);
                asm volatile("cp.async.commit_group;");
            }
        }
    }

    // epilogue: stage, convert fp16 (unscaled), store
#pragma unroll
    for (int i = 0; i < 2; i++) {
#pragma unroll
        for (int j = 0; j < 4; j++) {
            wmma::store_matrix_sync(&stage[wid][0][0], acc[i][j], 20, wmma::mem_row_major);
            __syncwarp();
            int r = row0 + warp_m * 32 + i * 16 + (lane >> 1);
            int c = warp_n * 64 + j * 16 + (lane & 1) * 8;
            if (r < N_NODES) {
                const float* sp = &stage[wid][lane >> 1][(lane & 1) * 8];
                __half2 p0 = __floats2half2_rn(sp[0], sp[1]);
                __half2 p1 = __floats2half2_rn(sp[2], sp[3]);
                __half2 p2 = __floats2half2_rn(sp[4], sp[5]);
                __half2 p3 = __floats2half2_rn(sp[6], sp[7]);
                uint4 pk;
                pk.x = *(const uint32_t*)&p0;
                pk.y = *(const uint32_t*)&p1;
                pk.z = *(const uint32_t*)&p2;
                pk.w = *(const uint32_t*)&p3;
                *(uint4*)&g_h1h[(size_t)r * HIDDEN + c] = pk;
            }
            __syncwarp();
        }
    }
}

// ---------------------------------------------------------------------------
// agg1 + layer2 fused (CSR): one warp per node; per-edge dinv[s] weight.
// acc = dinv[d]*h1[d] + sum_s dinv[s]*h1[s];  agg = dinv[d]*acc
// ---------------------------------------------------------------------------
__global__ void agg1_fused_kernel(const float* __restrict__ b1,
                                  const float* __restrict__ W2) {
    int warp = (blockIdx.x * blockDim.x + threadIdx.x) >> 5;
    int lane = threadIdx.x & 31;
    if (warp >= N_NODES) return;
    int node  = warp;
    int start = g_rowstart[node];
    int end   = g_rowstart[node + 1];
    float dd  = g_dinv[node];

    float4 acc;
    {   // self-loop term: dinv[d] * h1[d]
        uint2 v = ((const uint2*)(g_h1h + (size_t)node * HIDDEN))[lane];
        float2 f0 = __half22float2(*reinterpret_cast<__half2*>(&v.x));
        float2 f1 = __half22float2(*reinterpret_cast<__half2*>(&v.y));
        acc = make_float4(dd * f0.x, dd * f0.y, dd * f1.x, dd * f1.y);
    }

    for (int base = start; base < end; base += 32) {
        int idx = base + lane;
        int   s_l = 0;
        float d_l = 0.f;
        if (idx < end) {
            s_l = g_csr_src[idx];
            d_l = g_dinv[s_l];
        }
        int m = min(32, end - base);
        int j = 0;
        for (; j + 8 <= m; j += 8) {
            uint2 v[8];
            float w[8];
#pragma unroll
            for (int u = 0; u < 8; u++) {
                int s = __shfl_sync(0xffffffffu, s_l, j + u);
                w[u]  = __shfl_sync(0xffffffffu, d_l, j + u);
                v[u]  = ((const uint2*)(g_h1h + (size_t)s * HIDDEN))[lane];
            }
#pragma unroll
            for (int u = 0; u < 8; u++) {
                float2 f0 = __half22float2(*reinterpret_cast<__half2*>(&v[u].x));
                float2 f1 = __half22float2(*reinterpret_cast<__half2*>(&v[u].y));
                acc.x = fmaf(w[u], f0.x, acc.x);
                acc.y = fmaf(w[u], f0.y, acc.y);
                acc.z = fmaf(w[u], f1.x, acc.z);
                acc.w = fmaf(w[u], f1.y, acc.w);
            }
        }
        for (; j + 4 <= m; j += 4) {
            uint2 v[4];
            float w[4];
#pragma unroll
            for (int u = 0; u < 4; u++) {
                int s = __shfl_sync(0xffffffffu, s_l, j + u);
                w[u]  = __shfl_sync(0xffffffffu, d_l, j + u);
                v[u]  = ((const uint2*)(g_h1h + (size_t)s * HIDDEN))[lane];
            }
#pragma unroll
            for (int u = 0; u < 4; u++) {
                float2 f0 = __half22float2(*reinterpret_cast<__half2*>(&v[u].x));
                float2 f1 = __half22float2(*reinterpret_cast<__half2*>(&v[u].y));
                acc.x = fmaf(w[u], f0.x, acc.x);
                acc.y = fmaf(w[u], f0.y, acc.y);
                acc.z = fmaf(w[u], f1.x, acc.z);
                acc.w = fmaf(w[u], f1.y, acc.w);
            }
        }
        for (; j < m; j++) {
            int   s = __shfl_sync(0xffffffffu, s_l, j);
            float w = __shfl_sync(0xffffffffu, d_l, j);
            uint2 v = ((const uint2*)(g_h1h + (size_t)s * HIDDEN))[lane];
            float2 f0 = __half22float2(*reinterpret_cast<__half2*>(&v.x));
            float2 f1 = __half22float2(*reinterpret_cast<__half2*>(&v.y));
            acc.x = fmaf(w, f0.x, acc.x);
            acc.y = fmaf(w, f0.y, acc.y);
            acc.z = fmaf(w, f1.x, acc.z);
            acc.w = fmaf(w, f1.y, acc.w);
        }
    }

    float4 bb = ((const float4*)b1)[lane];
    float h0 = fmaxf(fmaf(dd, acc.x, bb.x), 0.f);
    float h1v = fmaxf(fmaf(dd, acc.y, bb.y), 0.f);
    float h2v = fmaxf(fmaf(dd, acc.z, bb.z), 0.f);
    float h3 = fmaxf(fmaf(dd, acc.w, bb.w), 0.f);
    const float4* wv = (const float4*)W2;   // [128][2] row-major
    float4 wa = wv[2 * lane], wb = wv[2 * lane + 1];
    float o0 = h0 * wa.x + h1v * wa.z + h2v * wb.x + h3 * wb.z;
    float o1 = h0 * wa.y + h1v * wa.w + h2v * wb.y + h3 * wb.w;
#pragma unroll
    for (int off = 16; off; off >>= 1) {
        o0 += __shfl_xor_sync(0xffffffffu, o0, off);
        o1 += __shfl_xor_sync(0xffffffffu, o1, off);
    }
    if (lane == 0) {
        g_h2s[2 * node]     = dd * o0;   // pre-scaled for layer-2 aggregation
        g_h2s[2 * node + 1] = dd * o1;
    }
}

// ---------------------------------------------------------------------------
// agg2: 4 nodes per warp (8 lanes each)
// ---------------------------------------------------------------------------
__global__ void agg2_csr_kernel(const float* __restrict__ b2,
                                float* __restrict__ out) {
    int warp = (blockIdx.x * blockDim.x + threadIdx.x) >> 5;
    int lane = threadIdx.x & 31;
    int grp  = lane >> 3;
    int gl   = lane & 7;
    int node = warp * 4 + grp;
    bool valid = (node < N_NODES);

    float a0 = 0.f, a1 = 0.f;
    if (valid) {
        int start = g_rowstart[node];
        int end   = g_rowstart[node + 1];
        for (int idx = start + gl; idx < end; idx += 8) {
            int s    = g_csr_src[idx];
            float2 hh = *(const float2*)(g_h2s + 2 * (size_t)s);
            a0 += hh.x;
            a1 += hh.y;
        }
        if (gl == 0) {
            float2 hs = *(const float2*)(g_h2s + 2 * (size_t)node);
            a0 += hs.x;
            a1 += hs.y;
        }
    }
#pragma unroll
    for (int off = 4; off; off >>= 1) {
        a0 += __shfl_xor_sync(0xffffffffu, a0, off);
        a1 += __shfl_xor_sync(0xffffffffu, a1, off);
    }
    if (valid && gl == 0) {
        float dd = g_dinv[node];
        out[2 * node]     = fmaf(dd, a0, b2[0]);
        out[2 * node + 1] = fmaf(dd, a1, b2[1]);
    }
}

// ---------------------------------------------------------------------------
extern "C" void kernel_launch(void* const* d_in, const int* in_sizes, int n_in,
                              void* d_out, int out_size) {
    const float* x  = (const float*)d_in[0];
    const int*   ei = (const int*)d_in[1];
    const float* W1 = (const float*)d_in[2];
    const float* b1 = (const float*)d_in[3];
    const float* W2 = (const float*)d_in[4];
    const float* b2 = (const float*)d_in[5];
    float*       out = (float*)d_out;

    const int* src = ei;
    const int* dst = ei + N_EDGES;

    static cudaStream_t s2 = nullptr;
    static cudaEvent_t evRoot, evFill;
    if (!s2) {
        cudaStreamCreateWithFlags(&s2, cudaStreamNonBlocking);
        cudaEventCreateWithFlags(&evRoot, cudaEventDisableTiming);
        cudaEventCreateWithFlags(&evFill, cudaEventDisableTiming);
        cudaFuncSetAttribute(gemm1_fp16_kernel,
                             cudaFuncAttributeMaxDynamicSharedMemorySize, SM_GEMM);
    }

    cudaEventRecord(evRoot, 0);
    cudaStreamWaitEvent(s2, evRoot, 0);

    // s2: degree / dinv / CSR build (runs fully concurrent with gemm)
    zero_cnt_kernel<<<(N_NODES + 255) / 256, 256, 0, s2>>>();
    hist_kernel<<<(N_EDGES / 4 + 255) / 256, 256, 0, s2>>>(dst);
    dinv_kernel<<<(N_NODES + 255) / 256, 256, 0, s2>>>();
    scan1_kernel<<<NB_SCAN, SCAN_BLOCK, 0, s2>>>();
    scan2_kernel<<<1, SCAN_BLOCK, 0, s2>>>();
    scan3_kernel<<<(N_NODES + 1 + 255) / 256, 256, 0, s2>>>();
    fill_edges_kernel<<<(N_EDGES + 255) / 256, 256, 0, s2>>>(src, dst);
    cudaEventRecord(evFill, s2);

    // stream 0: W1 conversion then gemm immediately (no dinv dependency)
    convert_w_kernel<<<(192 * (HIDDEN / 2) + 255) / 256, 256>>>(W1);
    gemm1_fp16_kernel<<<(N_NODES + 127) / 128, 256, SM_GEMM>>>(x);

    // aggregation needs gemm (stream 0) + CSR/dinv (s2)
    cudaStreamWaitEvent(0, evFill, 0);
    agg1_fused_kernel<<<(N_NODES * 32 + 255) / 256, 256>>>(b1, W2);
    agg2_csr_kernel<<<(N_NODES * 8 + 255) / 256, 256>>>(b2, out);
}

// round 16
// speedup vs baseline: 1.1416x; 1.1416x over previous
#include <cuda_runtime.h>
#include <cuda_fp16.h>
#include <mma.h>
#include <cstdint>

using namespace nvcuda;

#define N_NODES 100000
#define N_EDGES 1600000
#define IN_DIM  165
#define HIDDEN  128
#define OUT_DIM 2

#define KSTEP  32
#define NITER  6              // 192 covered, zero-filled

#define SCAN_BLOCK 512
#define NB_SCAN ((N_NODES + SCAN_BLOCK - 1) / SCAN_BLOCK)

// gemm dynamic smem layout: Ah 2x128x40 half (20480) | Bs 192x136 half (52224)
// epilogue stage (8x16x20 fp32 = 10240) overlays Ah[0]
#define SM_AH    0
#define SM_BS    20480
#define SM_GEMM  (20480 + 52224)   // 72704 B

// ---------------------------------------------------------------------------
// Static scratch
// ---------------------------------------------------------------------------
__device__ __align__(16)  __half g_w1h[192 * HIDDEN];
__device__ __align__(256) __half g_h1h[(size_t)N_NODES * HIDDEN];   // dinv-scaled fp16 h1
__device__ float g_h2s[(size_t)N_NODES * OUT_DIM];                  // dinv-scaled h2
__device__ float g_dinv[N_NODES];
__device__ int   g_cnt[N_NODES];
__device__ int   g_rowstart[N_NODES + 1];
__device__ int   g_cursor[N_NODES];
__device__ int   g_bsum[NB_SCAN];
__device__ int   g_bsum_ex[NB_SCAN];
__device__ int   g_csr_src[N_EDGES];

__device__ __forceinline__ void cp_async16(void* smem_dst, const void* gmem_src,
                                           int src_bytes) {
    uint32_t s = (uint32_t)__cvta_generic_to_shared(smem_dst);
    asm volatile("cp.async.cg.shared.global [%0], [%1], 16, %2;"
                 :: "r"(s), "l"(gmem_src), "r"(src_bytes));
}

// ---------------------------------------------------------------------------
// W1 fp16 conversion (tiny)
// ---------------------------------------------------------------------------
__global__ void convert_w_kernel(const float* __restrict__ W) {
    int i = blockIdx.x * blockDim.x + threadIdx.x;
    if (i >= 192 * (HIDDEN / 2)) return;
    int r  = i / (HIDDEN / 2);
    int c2 = i % (HIDDEN / 2);
    int c  = c2 * 2;
    float a = (r < IN_DIM) ? W[(size_t)r * HIDDEN + c]     : 0.f;
    float b = (r < IN_DIM) ? W[(size_t)r * HIDDEN + c + 1] : 0.f;
    ((__half2*)g_w1h)[i] = __floats2half2_rn(a, b);
}

// ---------------------------------------------------------------------------
// degree / CSR build
// ---------------------------------------------------------------------------
__global__ void zero_cnt_kernel() {
    int i = blockIdx.x * blockDim.x + threadIdx.x;
    if (i < N_NODES) g_cnt[i] = 0;
}

__global__ void hist_kernel(const int* __restrict__ dst) {
    int i = blockIdx.x * blockDim.x + threadIdx.x;
    if (i >= N_EDGES / 4) return;
    int4 d = ((const int4*)dst)[i];
    atomicAdd(&g_cnt[d.x], 1);
    atomicAdd(&g_cnt[d.y], 1);
    atomicAdd(&g_cnt[d.z], 1);
    atomicAdd(&g_cnt[d.w], 1);
}

__global__ void dinv_kernel() {
    int i = blockIdx.x * blockDim.x + threadIdx.x;
    if (i < N_NODES) g_dinv[i] = rsqrtf((float)(g_cnt[i] + 1));
}

__global__ void scan1_kernel() {
    __shared__ int s0[SCAN_BLOCK], s1[SCAN_BLOCK];
    int t = threadIdx.x;
    int i = blockIdx.x * SCAN_BLOCK + t;
    int v = (i < N_NODES) ? g_cnt[i] : 0;
    int* a = s0; int* b = s1;
    a[t] = v;
    __syncthreads();
#pragma unroll
    for (int off = 1; off < SCAN_BLOCK; off <<= 1) {
        b[t] = (t >= off) ? a[t] + a[t - off] : a[t];
        __syncthreads();
        int* tmp = a; a = b; b = tmp;
    }
    if (i < N_NODES) g_rowstart[i] = a[t] - v;
    if (t == SCAN_BLOCK - 1) g_bsum[blockIdx.x] = a[t];
}

__global__ void scan2_kernel() {
    __shared__ int s0[SCAN_BLOCK], s1[SCAN_BLOCK];
    int t = threadIdx.x;
    int v = (t < NB_SCAN) ? g_bsum[t] : 0;
    int* a = s0; int* b = s1;
    a[t] = v;
    __syncthreads();
#pragma unroll
    for (int off = 1; off < SCAN_BLOCK; off <<= 1) {
        b[t] = (t >= off) ? a[t] + a[t - off] : a[t];
        __syncthreads();
        int* tmp = a; a = b; b = tmp;
    }
    if (t < NB_SCAN) g_bsum_ex[t] = a[t] - v;
}

__global__ void scan3_kernel() {
    int i = blockIdx.x * blockDim.x + threadIdx.x;
    if (i < N_NODES) {
        int r = g_rowstart[i] + g_bsum_ex[i / SCAN_BLOCK];
        g_rowstart[i] = r;
        g_cursor[i]   = r;
    } else if (i == N_NODES) {
        g_rowstart[N_NODES] = N_EDGES;
    }
}

__global__ void fill_edges_kernel(const int* __restrict__ src,
                                  const int* __restrict__ dst) {
    int e = blockIdx.x * blockDim.x + threadIdx.x;
    if (e < N_EDGES) {
        int d   = dst[e];
        int pos = atomicAdd(&g_cursor[d], 1);
        g_csr_src[pos] = src[e];
    }
}

// ---------------------------------------------------------------------------
// GEMM1: h1h[r,:] = dinv[r] * fp16(x[r,:] @ W1)
// A path: gmem -> registers -> fp16 smem (no fp32 staging buffer).
// B: entire fp16 W1 (192x128) resident in smem, loaded once.
// Mainloop: MMA -> convert next A tile -> prefetch regs -> ONE sync.
// ---------------------------------------------------------------------------
__global__ void gemm1_fp16_kernel(const float* __restrict__ X) {
    extern __shared__ __align__(16) unsigned char sraw[];
    __half (*Ah)[128][40] = reinterpret_cast<__half(*)[128][40]>(sraw + SM_AH);
    __half (*Bs)[136]     = reinterpret_cast<__half(*)[136]>(sraw + SM_BS);   // [192][136]
    float  (*stage)[16][20] = reinterpret_cast<float(*)[16][20]>(sraw);       // overlays Ah[0]

    const int tid    = threadIdx.x;
    const int wid    = tid >> 5;
    const int lane   = tid & 31;
    const int warp_m = wid & 3;
    const int warp_n = wid >> 2;
    const int row0   = blockIdx.x * 128;

    // thread (wid, lane) owns rows wid, wid+8, ..., wid+120 at column lane
    float fA[16];
    auto prefetch = [&](int k0) {
#pragma unroll
        for (int u = 0; u < 16; u++) {
            int r  = wid + u * 8;
            int gr = row0 + r, gc = k0 + lane;
            fA[u] = (gr < N_NODES && gc < IN_DIM)
                        ? __ldg(X + (size_t)gr * IN_DIM + gc) : 0.f;
        }
    };
    auto convertA = [&](int buf) {
#pragma unroll
        for (int u = 0; u < 16; u++) {
            int r = wid + u * 8;
            Ah[buf][r][lane] = __float2half_rn(fA[u]);
        }
    };

    // prologue: Bs fully loaded (192 rows x 16 chunks = 3072 / 256 = 12 each)
    prefetch(0);
#pragma unroll
    for (int t = 0; t < 12; t++) {
        int idx = tid + t * 256;
        int r = idx >> 4, ch = idx & 15;
        cp_async16(&Bs[r][ch * 8], g_w1h + (size_t)r * HIDDEN + ch * 8, 16);
    }
    asm volatile("cp.async.commit_group;");

    wmma::fragment<wmma::accumulator, 16, 16, 16, float> acc[2][4];
#pragma unroll
    for (int i = 0; i < 2; i++)
#pragma unroll
        for (int j = 0; j < 4; j++) wmma::fill_fragment(acc[i][j], 0.f);

    convertA(0);                 // stalls on fA tile-0 loads once
    prefetch(KSTEP);             // tile 1 in flight
    asm volatile("cp.async.wait_group 0;");
    __syncthreads();             // Ah[0] + Bs visible

    for (int it = 0; it < NITER; it++) {
        int buf = it & 1;
        wmma::fragment<wmma::matrix_a, 16, 16, 16, __half, wmma::row_major> af[2];
        wmma::fragment<wmma::matrix_b, 16, 16, 16, __half, wmma::row_major> bf[4];
#pragma unroll
        for (int kk = 0; kk < KSTEP; kk += 16) {
            int kg = it * KSTEP + kk;
#pragma unroll
            for (int i = 0; i < 2; i++)
                wmma::load_matrix_sync(af[i], &Ah[buf][warp_m * 32 + i * 16][kk], 40);
#pragma unroll
            for (int j = 0; j < 4; j++)
                wmma::load_matrix_sync(bf[j], &Bs[kg][warp_n * 64 + j * 16], 136);
#pragma unroll
            for (int i = 0; i < 2; i++)
#pragma unroll
                for (int j = 0; j < 4; j++)
                    wmma::mma_sync(acc[i][j], af[i], bf[j], acc[i][j]);
        }
        if (it + 1 < NITER) {
            // Ah[(it+1)&1] was last read by MMA(it-1), separated by prev sync
            convertA((it + 1) & 1);
            if (it + 2 < NITER) prefetch((it + 2) * KSTEP);
            __syncthreads();
        }
    }

    // epilogue: stage overlays Ah[0]; final MMA (it=5) read Ah[1] — disjoint
#pragma unroll
    for (int i = 0; i < 2; i++) {
#pragma unroll
        for (int j = 0; j < 4; j++) {
            wmma::store_matrix_sync(&stage[wid][0][0], acc[i][j], 20, wmma::mem_row_major);
            __syncwarp();
            int r = row0 + warp_m * 32 + i * 16 + (lane >> 1);
            int c = warp_n * 64 + j * 16 + (lane & 1) * 8;
            if (r < N_NODES) {
                float di = g_dinv[r];
                const float* sp = &stage[wid][lane >> 1][(lane & 1) * 8];
                __half2 p0 = __floats2half2_rn(sp[0] * di, sp[1] * di);
                __half2 p1 = __floats2half2_rn(sp[2] * di, sp[3] * di);
                __half2 p2 = __floats2half2_rn(sp[4] * di, sp[5] * di);
                __half2 p3 = __floats2half2_rn(sp[6] * di, sp[7] * di);
                uint4 pk;
                pk.x = *(const uint32_t*)&p0;
                pk.y = *(const uint32_t*)&p1;
                pk.z = *(const uint32_t*)&p2;
                pk.w = *(const uint32_t*)&p3;
                *(uint4*)&g_h1h[(size_t)r * HIDDEN + c] = pk;
            }
            __syncwarp();
        }
    }
}

// ---------------------------------------------------------------------------
// agg1 + layer2 fused (CSR): one warp per node; HADD2 pair summation (R14)
// ---------------------------------------------------------------------------
__global__ void agg1_fused_kernel(const float* __restrict__ b1,
                                  const float* __restrict__ W2) {
    int warp = (blockIdx.x * blockDim.x + threadIdx.x) >> 5;
    int lane = threadIdx.x & 31;
    if (warp >= N_NODES) return;
    int node  = warp;
    int start = g_rowstart[node];
    int end   = g_rowstart[node + 1];

    float4 acc;
    {   // self-loop term
        uint2 v = ((const uint2*)(g_h1h + (size_t)node * HIDDEN))[lane];
        float2 f0 = __half22float2(*reinterpret_cast<__half2*>(&v.x));
        float2 f1 = __half22float2(*reinterpret_cast<__half2*>(&v.y));
        acc = make_float4(f0.x, f0.y, f1.x, f1.y);
    }

    for (int base = start; base < end; base += 32) {
        int idx = base + lane;
        int s_l = (idx < end) ? g_csr_src[idx] : 0;
        int m = min(32, end - base);
        int j = 0;
        for (; j + 8 <= m; j += 8) {
            uint2 v[8];
#pragma unroll
            for (int u = 0; u < 8; u++) {
                int s = __shfl_sync(0xffffffffu, s_l, j + u);
                v[u] = ((const uint2*)(g_h1h + (size_t)s * HIDDEN))[lane];
            }
#pragma unroll
            for (int u = 0; u < 4; u++) {
                __half2 lo = __hadd2(*reinterpret_cast<__half2*>(&v[2 * u].x),
                                     *reinterpret_cast<__half2*>(&v[2 * u + 1].x));
                __half2 hi = __hadd2(*reinterpret_cast<__half2*>(&v[2 * u].y),
                                     *reinterpret_cast<__half2*>(&v[2 * u + 1].y));
                float2 f0 = __half22float2(lo);
                float2 f1 = __half22float2(hi);
                acc.x += f0.x; acc.y += f0.y; acc.z += f1.x; acc.w += f1.y;
            }
        }
        for (; j + 2 <= m; j += 2) {
            int s0 = __shfl_sync(0xffffffffu, s_l, j);
            int s1 = __shfl_sync(0xffffffffu, s_l, j + 1);
            uint2 v0 = ((const uint2*)(g_h1h + (size_t)s0 * HIDDEN))[lane];
            uint2 v1 = ((const uint2*)(g_h1h + (size_t)s1 * HIDDEN))[lane];
            __half2 lo = __hadd2(*reinterpret_cast<__half2*>(&v0.x),
                                 *reinterpret_cast<__half2*>(&v1.x));
            __half2 hi = __hadd2(*reinterpret_cast<__half2*>(&v0.y),
                                 *reinterpret_cast<__half2*>(&v1.y));
            float2 f0 = __half22float2(lo);
            float2 f1 = __half22float2(hi);
            acc.x += f0.x; acc.y += f0.y; acc.z += f1.x; acc.w += f1.y;
        }
        if (j < m) {
            int s = __shfl_sync(0xffffffffu, s_l, j);
            uint2 v = ((const uint2*)(g_h1h + (size_t)s * HIDDEN))[lane];
            float2 f0 = __half22float2(*reinterpret_cast<__half2*>(&v.x));
            float2 f1 = __half22float2(*reinterpret_cast<__half2*>(&v.y));
            acc.x += f0.x; acc.y += f0.y; acc.z += f1.x; acc.w += f1.y;
        }
    }

    float dd = g_dinv[node];
    float4 bb = ((const float4*)b1)[lane];
    float h0 = fmaxf(fmaf(dd, acc.x, bb.x), 0.f);
    float h1v = fmaxf(fmaf(dd, acc.y, bb.y), 0.f);
    float h2v = fmaxf(fmaf(dd, acc.z, bb.z), 0.f);
    float h3 = fmaxf(fmaf(dd, acc.w, bb.w), 0.f);
    const float4* wv = (const float4*)W2;   // [128][2] row-major
    float4 wa = wv[2 * lane], wb = wv[2 * lane + 1];
    float o0 = h0 * wa.x + h1v * wa.z + h2v * wb.x + h3 * wb.z;
    float o1 = h0 * wa.y + h1v * wa.w + h2v * wb.y + h3 * wb.w;
#pragma unroll
    for (int off = 16; off; off >>= 1) {
        o0 += __shfl_xor_sync(0xffffffffu, o0, off);
        o1 += __shfl_xor_sync(0xffffffffu, o1, off);
    }
    if (lane == 0) {
        g_h2s[2 * node]     = dd * o0;
        g_h2s[2 * node + 1] = dd * o1;
    }
}

// ---------------------------------------------------------------------------
// agg2: 4 nodes per warp (8 lanes each)
// ---------------------------------------------------------------------------
__global__ void agg2_csr_kernel(const float* __restrict__ b2,
                                float* __restrict__ out) {
    int warp = (blockIdx.x * blockDim.x + threadIdx.x) >> 5;
    int lane = threadIdx.x & 31;
    int grp  = lane >> 3;
    int gl   = lane & 7;
    int node = warp * 4 + grp;
    bool valid = (node < N_NODES);

    float a0 = 0.f, a1 = 0.f;
    if (valid) {
        int start = g_rowstart[node];
        int end   = g_rowstart[node + 1];
        for (int idx = start + gl; idx < end; idx += 8) {
            int s    = g_csr_src[idx];
            float2 hh = *(const float2*)(g_h2s + 2 * (size_t)s);
            a0 += hh.x;
            a1 += hh.y;
        }
        if (gl == 0) {
            float2 hs = *(const float2*)(g_h2s + 2 * (size_t)node);
            a0 += hs.x;
            a1 += hs.y;
        }
    }
#pragma unroll
    for (int off = 4; off; off >>= 1) {
        a0 += __shfl_xor_sync(0xffffffffu, a0, off);
        a1 += __shfl_xor_sync(0xffffffffu, a1, off);
    }
    if (valid && gl == 0) {
        float dd = g_dinv[node];
        out[2 * node]     = fmaf(dd, a0, b2[0]);
        out[2 * node + 1] = fmaf(dd, a1, b2[1]);
    }
}

// ---------------------------------------------------------------------------
extern "C" void kernel_launch(void* const* d_in, const int* in_sizes, int n_in,
                              void* d_out, int out_size) {
    const float* x  = (const float*)d_in[0];
    const int*   ei = (const int*)d_in[1];
    const float* W1 = (const float*)d_in[2];
    const float* b1 = (const float*)d_in[3];
    const float* W2 = (const float*)d_in[4];
    const float* b2 = (const float*)d_in[5];
    float*       out = (float*)d_out;

    const int* src = ei;
    const int* dst = ei + N_EDGES;

    static cudaStream_t s2 = nullptr;
    static cudaEvent_t evRoot, evDinv, evFill;
    if (!s2) {
        cudaStreamCreateWithFlags(&s2, cudaStreamNonBlocking);
        cudaEventCreateWithFlags(&evRoot, cudaEventDisableTiming);
        cudaEventCreateWithFlags(&evDinv, cudaEventDisableTiming);
        cudaEventCreateWithFlags(&evFill, cudaEventDisableTiming);
        cudaFuncSetAttribute(gemm1_fp16_kernel,
                             cudaFuncAttributeMaxDynamicSharedMemorySize, SM_GEMM);
    }

    cudaEventRecord(evRoot, 0);
    cudaStreamWaitEvent(s2, evRoot, 0);

    // s2: degree / dinv / CSR build
    zero_cnt_kernel<<<(N_NODES + 255) / 256, 256, 0, s2>>>();
    hist_kernel<<<(N_EDGES / 4 + 255) / 256, 256, 0, s2>>>(dst);
    dinv_kernel<<<(N_NODES + 255) / 256, 256, 0, s2>>>();
    cudaEventRecord(evDinv, s2);
    scan1_kernel<<<NB_SCAN, SCAN_BLOCK, 0, s2>>>();
    scan2_kernel<<<1, SCAN_BLOCK, 0, s2>>>();
    scan3_kernel<<<(N_NODES + 1 + 255) / 256, 256, 0, s2>>>();
    fill_edges_kernel<<<(N_EDGES + 255) / 256, 256, 0, s2>>>(src, dst);
    cudaEventRecord(evFill, s2);

    // stream 0: W1 conversion (tiny) concurrent with s2
    convert_w_kernel<<<(192 * (HIDDEN / 2) + 255) / 256, 256>>>(W1);

    // gemm needs conv_w (stream 0) + dinv (s2); CSR fill continues under it
    cudaStreamWaitEvent(0, evDinv, 0);
    gemm1_fp16_kernel<<<(N_NODES + 127) / 128, 256, SM_GEMM>>>(x);

    cudaStreamWaitEvent(0, evFill, 0);
    agg1_fused_kernel<<<(N_NODES * 32 + 255) / 256, 256>>>(b1, W2);
    agg2_csr_kernel<<<(N_NODES * 8 + 255) / 256, 256>>>(b2, out);
}